// round 1
// baseline (speedup 1.0000x reference)
#include <cuda_runtime.h>
#include <cstdint>

// Problem constants (fixed-shape problem)
#define BATCH 2
#define NN    2048
#define NODES (BATCH * NN)          // 4096
#define FELEMS ((size_t)BATCH * NN * NN)  // 8,388,608

// ---------------- device scratch (allowed: __device__ globals) ----------------
__device__ __align__(16) float g_d[FELEMS];        // d = F1 - F0, 33.5 MB
__device__ __align__(16) float g_s1[2][NODES];     // double-buffered qS[...,1]
__device__ __align__(16) float g_c0[2][NODES];     // double-buffered qC[...,0]
__device__ __align__(16) float g_A[NODES];         // sum_y qF1 * s0[y]
__device__ __align__(16) float g_Bv[NODES];        // sum_x qF1 * s1[x]
__device__ unsigned g_counter;                     // last-block ticket (self-resetting)

__device__ __forceinline__ float sigmoidf(float z) {
    float e = __expf(-z);
    return __fdividef(1.0f, 1.0f + e);
}

// ---------------- kernel 1: d = F1-F0, init s1^0, c0^0, zero accumulators ----
__global__ void __launch_bounds__(256) precompute_kernel(
    const float* __restrict__ S, const float* __restrict__ C,
    const float* __restrict__ F)
{
    int gtid = blockIdx.x * blockDim.x + threadIdx.x;
    if (gtid < NODES) {
        g_s1[0][gtid] = sigmoidf(S[2 * gtid + 1] - S[2 * gtid]);
        g_c0[0][gtid] = sigmoidf(C[2 * gtid] - C[2 * gtid + 1]);
        g_A[gtid]  = 0.0f;
        g_Bv[gtid] = 0.0f;
    }
    const float4* F4 = (const float4*)F;            // (F0,F1,F0,F1)
    float2* D2 = (float2*)g_d;
    const int total = (int)(FELEMS / 2);            // number of float4 reads
    const int stride = gridDim.x * blockDim.x;
    for (int i = gtid; i < total; i += stride) {
        float4 f = F4[i];
        float2 dd;
        dd.x = f.y - f.x;
        dd.y = f.w - f.z;
        D2[i] = dd;
    }
}

// ---------------- kernel 2 (x5): qF1 reductions + fused s/c update ------------
// Block: 512 threads, 8 rows x 2048 cols. Each thread owns 4 fixed columns.
__global__ void __launch_bounds__(512) iter_kernel(
    const float* __restrict__ S, const float* __restrict__ C,
    const float* __restrict__ W, int iter)
{
    const int tid = threadIdx.x;
    const int rowBase = blockIdx.x * 8;          // global row in [0, 4096)
    const int b = rowBase >> 11;
    const int colBase = tid * 4;                 // [0, 2048)
    const float w0 = W[0], w1 = W[1];
    const int cur = iter & 1, prv = cur ^ 1;
    const float w1p = (iter == 0) ? 0.0f : w1;   // first step: qF1 = sigmoid(d)

    // column-constant vectors for my 4 columns
    float4 s1c4 = *(const float4*)&g_s1[cur][b * NN + colBase];
    float4 s1p4 = *(const float4*)&g_s1[prv][b * NN + colBase];
    float s0c0 = 1.0f - s1c4.x, s0c1 = 1.0f - s1c4.y,
          s0c2 = 1.0f - s1c4.z, s0c3 = 1.0f - s1c4.w;
    float s0p0 = 1.0f - s1p4.x, s0p1 = 1.0f - s1p4.y,
          s0p2 = 1.0f - s1p4.z, s0p3 = 1.0f - s1p4.w;

    float col0 = 0.f, col1 = 0.f, col2 = 0.f, col3 = 0.f;
    float rowacc[8];

#pragma unroll
    for (int r = 0; r < 8; r++) {
        const int row = rowBase + r;
        const float a = w1p * g_s1[prv][row];    // broadcast load
        const float m = g_s1[cur][row];
        float4 d4 = *(const float4*)&g_d[(size_t)row * NN + colBase];
        float q0 = sigmoidf(d4.x - a * s0p0);
        float q1 = sigmoidf(d4.y - a * s0p1);
        float q2 = sigmoidf(d4.z - a * s0p2);
        float q3 = sigmoidf(d4.w - a * s0p3);
        rowacc[r] = q0 * s0c0 + q1 * s0c1 + q2 * s0c2 + q3 * s0c3;
        col0 += q0 * m; col1 += q1 * m; col2 += q2 * m; col3 += q3 * m;
    }

    // row reductions: 8 rows x (16 warps)
    __shared__ float sred[8][16];
    const int lane = tid & 31, warp = tid >> 5;
#pragma unroll
    for (int r = 0; r < 8; r++) {
        float v = rowacc[r];
        v += __shfl_down_sync(0xffffffffu, v, 16);
        v += __shfl_down_sync(0xffffffffu, v, 8);
        v += __shfl_down_sync(0xffffffffu, v, 4);
        v += __shfl_down_sync(0xffffffffu, v, 2);
        v += __shfl_down_sync(0xffffffffu, v, 1);
        if (lane == 0) sred[r][warp] = v;
    }
    __syncthreads();
    if (tid < 8) {
        float v = 0.0f;
#pragma unroll
        for (int w = 0; w < 16; w++) v += sred[tid][w];
        g_A[rowBase + tid] = v;                  // direct store, no atomic needed
    }

    // column partial sums -> global (spread addresses)
    atomicAdd(&g_Bv[b * NN + colBase + 0], col0);
    atomicAdd(&g_Bv[b * NN + colBase + 1], col1);
    atomicAdd(&g_Bv[b * NN + colBase + 2], col2);
    atomicAdd(&g_Bv[b * NN + colBase + 3], col3);

    // ---- fused tail: last block computes s1^{k+1}, c0^{k+1}, re-zeros Bv ----
    __threadfence();
    __shared__ int isLast;
    if (tid == 0) isLast = (atomicAdd(&g_counter, 1u) == gridDim.x - 1);
    __syncthreads();
    if (isLast) {
        if (iter < 4) {
            const int nxt = prv;
            for (int i = tid; i < NODES; i += 512) {
                float Av  = g_A[i];
                float Bvv = g_Bv[i];
                float s1k = g_s1[cur][i];
                float c0k = g_c0[cur][i];
                float s1n = sigmoidf((S[2 * i + 1] + w1 * Bvv) -
                                     (S[2 * i] + w0 * c0k + w1 * Av));
                float c0n = sigmoidf(C[2 * i] - C[2 * i + 1] - w0 * s1k);
                g_s1[nxt][i] = s1n;
                g_c0[nxt][i] = c0n;
                g_Bv[i] = 0.0f;
            }
        }
        if (tid == 0) g_counter = 0;             // replay-safe reset
    }
}

// ---------------- kernel 3: final outputs -------------------------------------
// out layout: [S: 8192][C: 8192][F: 16,777,216] floats
__global__ void __launch_bounds__(256) final_kernel(
    const float* __restrict__ S, const float* __restrict__ C,
    const float* __restrict__ F, const float* __restrict__ W,
    float* __restrict__ out)
{
    const float w0 = W[0], w1 = W[1];
    const int row = blockIdx.x;                  // 0..4095
    const int b = row >> 11;
    const float a = w1 * g_s1[0][row];           // s1^4 lives in buffer 0
    const float4* Fr = (const float4*)(F + (size_t)row * (2 * NN));
    float4* Or = (float4*)(out + 16384 + (size_t)row * (2 * NN));
    const float* s1col = &g_s1[0][b * NN];
    for (int i = threadIdx.x; i < NN / 2; i += 256) {   // float4 = 2 (F0,F1) pairs
        float4 f = Fr[i];
        float2 s = *(const float2*)&s1col[2 * i];
        f.x += a * (1.0f - s.x);
        f.z += a * (1.0f - s.y);
        Or[i] = f;
    }
    if (blockIdx.x == 0) {
        for (int i = threadIdx.x; i < NODES; i += 256) {
            float s1 = g_s1[0][i];
            out[2 * i]     = S[2 * i] + w0 * g_c0[0][i] + w1 * g_A[i];
            out[2 * i + 1] = S[2 * i + 1] + w1 * g_Bv[i];
            out[8192 + 2 * i]     = C[2 * i];
            out[8192 + 2 * i + 1] = C[2 * i + 1] + w0 * s1;
        }
    }
}

extern "C" void kernel_launch(void* const* d_in, const int* in_sizes, int n_in,
                              void* d_out, int out_size)
{
    const float* S = (const float*)d_in[0];
    const float* C = (const float*)d_in[1];
    const float* F = (const float*)d_in[2];
    const float* W = (const float*)d_in[3];
    float* out = (float*)d_out;

    precompute_kernel<<<2048, 256>>>(S, C, F);
    for (int k = 0; k < 5; k++)
        iter_kernel<<<NODES / 8, 512>>>(S, C, W, k);
    final_kernel<<<NODES, 256>>>(S, C, F, W, out);
}